// round 2
// baseline (speedup 1.0000x reference)
#include <cuda_runtime.h>
#include <math.h>

static constexpr int NN = 100000;   // nodes (capacity)
static constexpr int EE = 1600000;  // edges (capacity)
static constexpr int DD = 64;

// Scratch (static device globals; no allocation in kernel_launch)
__device__ __align__(16) float g_z[(size_t)NN * DD];   // 25.6 MB accumulator
__device__ float g_as[NN], g_ad[NN];                   // per-node logit parts
__device__ int   g_mf[NN], g_mt[NN];                   // ordered-int maxes
__device__ float g_sf[NN], g_st[NN];                   // softmax denominators
__device__ float g_ef[EE], g_et[EE];                   // per-edge logits -> exps

__device__ __forceinline__ int ord(float f) {
    int i = __float_as_int(f);
    return i >= 0 ? i : (i ^ 0x7fffffff);
}
__device__ __forceinline__ float unord(int i) {
    return __int_as_float(i >= 0 ? i : (i ^ 0x7fffffff));
}

// ---------------------------------------------------------------------------
// K0: init accumulators
__global__ void k_init(int n) {
    int i = blockIdx.x * blockDim.x + threadIdx.x;
    if (i < n * DD) g_z[i] = 0.f;
    if (i < n) {
        g_sf[i] = 0.f;
        g_st[i] = 0.f;
        int m = ord(-INFINITY);
        g_mf[i] = m;
        g_mt[i] = m;
    }
}

// ---------------------------------------------------------------------------
// K1: per-node a_s = h[n] . wh[0:64], a_d = h[n] . wh[64:128]  (warp/node)
__global__ void k_node(const float* __restrict__ h, const float* __restrict__ wh, int n) {
    int gt = blockIdx.x * blockDim.x + threadIdx.x;
    int w = gt >> 5, lane = gt & 31;
    if (w >= n) return;
    float2 hv = *reinterpret_cast<const float2*>(h + (size_t)w * DD + lane * 2);
    float2 wa = *reinterpret_cast<const float2*>(wh + lane * 2);
    float2 wb = *reinterpret_cast<const float2*>(wh + DD + lane * 2);
    float ps = hv.x * wa.x + hv.y * wa.y;
    float pd = hv.x * wb.x + hv.y * wb.y;
#pragma unroll
    for (int o = 16; o; o >>= 1) {
        ps += __shfl_xor_sync(0xffffffffu, ps, o);
        pd += __shfl_xor_sync(0xffffffffu, pd, o);
    }
    if (lane == 0) { g_as[w] = ps; g_ad[w] = pd; }
}

// ---------------------------------------------------------------------------
// K2: per-edge logits + segment max (warp/edge; tax rows are L2-resident)
__global__ void k_edge1(const float* __restrict__ tax, const int* __restrict__ src,
                        const int* __restrict__ dst, int e) {
    int gt = blockIdx.x * blockDim.x + threadIdx.x;
    int w = gt >> 5, lane = gt & 31;
    if (w >= e) return;
    int s = src[w], d = dst[w];
    float2 ts = *reinterpret_cast<const float2*>(tax + (size_t)s * DD + lane * 2);
    float2 td = *reinterpret_cast<const float2*>(tax + (size_t)d * DD + lane * 2);
    float p = ts.x * td.x + ts.y * td.y;
#pragma unroll
    for (int o = 16; o; o >>= 1) p += __shfl_xor_sync(0xffffffffu, p, o);
    if (lane == 0) {
        float x = g_as[s] + g_ad[d];
        float wf = x >= 0.f ? x : 0.01f * x;   // leaky_relu, slope 0.01
        g_ef[w] = wf;
        g_et[w] = p;
        atomicMax(&g_mf[d], ord(wf));
        atomicMax(&g_mt[d], ord(p));
    }
}

// ---------------------------------------------------------------------------
// K3: per-edge exp + segment sum (thread/edge)
__global__ void k_edge2(const int* __restrict__ dst, int e) {
    int i = blockIdx.x * blockDim.x + threadIdx.x;
    if (i >= e) return;
    int d = dst[i];
    float ef = __expf(g_ef[i] - unord(g_mf[d]));
    float et = __expf(g_et[i] - unord(g_mt[d]));
    g_ef[i] = ef;
    g_et[i] = et;
    atomicAdd(&g_sf[d], ef);
    atomicAdd(&g_st[d], et);
}

// ---------------------------------------------------------------------------
// K4: alpha + scatter z[dst] += h[src]*alpha  (16 threads/edge, red.v4)
__global__ void k_edge3(const float* __restrict__ h, const int* __restrict__ src,
                        const int* __restrict__ dst, int e) {
    int gt = blockIdx.x * blockDim.x + threadIdx.x;
    int w = gt >> 4, l = gt & 15;
    if (w >= e) return;
    int s = src[w], d = dst[w];
    float a = 0.5f * (g_ef[w] / g_sf[d]) + 0.5f * (g_et[w] / g_st[d]);
    float4 hv = *reinterpret_cast<const float4*>(h + (size_t)s * DD + l * 4);
    float* zp = g_z + (size_t)d * DD + l * 4;
    asm volatile("red.global.add.v4.f32 [%0], {%1, %2, %3, %4};"
                 :: "l"(zp), "f"(hv.x * a), "f"(hv.y * a), "f"(hv.z * a), "f"(hv.w * a)
                 : "memory");
}

// ---------------------------------------------------------------------------
// K5: out = z @ W^T + b   (block = (64,4); W transposed into smem, conflict-free)
__global__ void k_out(const float* __restrict__ Ww, const float* __restrict__ Wb,
                      float* __restrict__ out, int n) {
    __shared__ float Ws[DD * DD];   // Ws[k*64 + c] = Ww[c*64 + k]
    __shared__ float bs[DD];
    int tid = threadIdx.y * 64 + threadIdx.x;   // 0..255
    for (int i = tid; i < DD * DD; i += 256) {
        int c = i >> 6, k = i & 63;
        Ws[k * DD + c] = Ww[i];
    }
    if (tid < DD) bs[tid] = Wb[tid];
    __syncthreads();
    int row = blockIdx.x * 4 + threadIdx.y;
    if (row >= n) return;
    int c = threadIdx.x;
    const float* zr = g_z + (size_t)row * DD;
    float acc = bs[c];
#pragma unroll
    for (int k = 0; k < DD; k += 4) {
        float4 zv = *reinterpret_cast<const float4*>(zr + k);
        acc += zv.x * Ws[(k + 0) * DD + c];
        acc += zv.y * Ws[(k + 1) * DD + c];
        acc += zv.z * Ws[(k + 2) * DD + c];
        acc += zv.w * Ws[(k + 3) * DD + c];
    }
    out[(size_t)row * DD + c] = acc;
}

// ---------------------------------------------------------------------------
extern "C" void kernel_launch(void* const* d_in, const int* in_sizes, int n_in,
                              void* d_out, int out_size) {
    const float* h   = (const float*)d_in[0];
    const float* tax = (const float*)d_in[1];
    const int*   src = (const int*)d_in[2];
    const int*   dst = (const int*)d_in[3];
    const float* wh  = (const float*)d_in[4];
    const float* Ww  = (const float*)d_in[5];
    const float* Wb  = (const float*)d_in[6];
    float* out = (float*)d_out;

    int n = in_sizes[0] / DD;
    int e = in_sizes[2];

    k_init<<<(n * DD + 255) / 256, 256>>>(n);
    k_node<<<(n * 32 + 255) / 256, 256>>>(h, wh, n);
    k_edge1<<<(int)(((long long)e * 32 + 255) / 256), 256>>>(tax, src, dst, e);
    k_edge2<<<(e + 255) / 256, 256>>>(dst, e);
    k_edge3<<<(int)(((long long)e * 16 + 255) / 256), 256>>>(h, src, dst, e);
    k_out<<<(n + 3) / 4, dim3(64, 4)>>>(Ww, Wb, out, n);
}

// round 3
// speedup vs baseline: 1.0984x; 1.0984x over previous
#include <cuda_runtime.h>
#include <math.h>

static constexpr int NN = 100000;   // nodes (capacity)
static constexpr int EE = 1600000;  // edges (capacity)
static constexpr int DD = 64;

// Scratch (static device globals; no allocation anywhere)
__device__ __align__(16) float g_z[(size_t)NN * DD];   // 25.6 MB z accumulator
__device__ float g_as[NN], g_ad[NN];                   // per-node logit halves
__device__ int   g_cnt[NN];                            // in-degree histogram
__device__ int   g_off[NN];                            // CSR row start
__device__ int   g_pos[NN];                            // scatter cursor -> row end
__device__ float g_ef[EE], g_et[EE];                   // logits -> exps -> alpha
__device__ int   g_src2[EE];                           // src sorted by dst

// ---------------------------------------------------------------------------
// K0: zero histogram
__global__ void k_init(int n) {
    int i = blockIdx.x * blockDim.x + threadIdx.x;
    if (i < n) g_cnt[i] = 0;
}

// ---------------------------------------------------------------------------
// K1: per-node a_s = h[n] . wh[0:64], a_d = h[n] . wh[64:128]  (warp/node)
__global__ void k_node(const float* __restrict__ h, const float* __restrict__ wh, int n) {
    int gt = blockIdx.x * blockDim.x + threadIdx.x;
    int w = gt >> 5, lane = gt & 31;
    if (w >= n) return;
    float2 hv = *reinterpret_cast<const float2*>(h + (size_t)w * DD + lane * 2);
    float2 wa = *reinterpret_cast<const float2*>(wh + lane * 2);
    float2 wb = *reinterpret_cast<const float2*>(wh + DD + lane * 2);
    float ps = hv.x * wa.x + hv.y * wa.y;
    float pd = hv.x * wb.x + hv.y * wb.y;
#pragma unroll
    for (int o = 16; o; o >>= 1) {
        ps += __shfl_xor_sync(0xffffffffu, ps, o);
        pd += __shfl_xor_sync(0xffffffffu, pd, o);
    }
    if (lane == 0) { g_as[w] = ps; g_ad[w] = pd; }
}

// ---------------------------------------------------------------------------
// K2: histogram of dst
__global__ void k_hist(const int* __restrict__ dst, int e) {
    int i = blockIdx.x * blockDim.x + threadIdx.x;
    if (i < e) atomicAdd(&g_cnt[dst[i]], 1);
}

// ---------------------------------------------------------------------------
// K3: exclusive scan of g_cnt -> g_off, g_pos   (single block, 1024 threads)
__global__ void k_scan(int n) {
    __shared__ int ssum[1024];
    int t = threadIdx.x;
    int C = (n + 1023) / 1024;
    int lo = t * C, hi = lo + C; if (hi > n) hi = n; if (lo > n) lo = n;
    int s = 0;
    for (int i = lo; i < hi; i++) s += g_cnt[i];
    ssum[t] = s;
    __syncthreads();
    // Hillis-Steele inclusive scan over 1024
    for (int d = 1; d < 1024; d <<= 1) {
        int v = (t >= d) ? ssum[t - d] : 0;
        __syncthreads();
        ssum[t] += v;
        __syncthreads();
    }
    int off = ssum[t] - s;   // exclusive prefix for this chunk
    for (int i = lo; i < hi; i++) {
        int c = g_cnt[i];
        g_off[i] = off;
        g_pos[i] = off;
        off += c;
    }
}

// ---------------------------------------------------------------------------
// K4: per-edge logits, scattered into CSR order (8 lanes/edge, float4 loads)
__global__ void k_edge1(const float* __restrict__ tax, const int* __restrict__ src,
                        const int* __restrict__ dst, int e) {
    int gt = blockIdx.x * blockDim.x + threadIdx.x;
    int w = gt >> 3, l = gt & 7;
    if (w >= e) return;
    int s = src[w], d = dst[w];
    const float4* ts = reinterpret_cast<const float4*>(tax + (size_t)s * DD);
    const float4* td = reinterpret_cast<const float4*>(tax + (size_t)d * DD);
    float4 a0 = ts[l * 2],     b0 = td[l * 2];
    float4 a1 = ts[l * 2 + 1], b1 = td[l * 2 + 1];
    float p = a0.x * b0.x + a0.y * b0.y + a0.z * b0.z + a0.w * b0.w
            + a1.x * b1.x + a1.y * b1.y + a1.z * b1.z + a1.w * b1.w;
#pragma unroll
    for (int o = 4; o; o >>= 1) p += __shfl_xor_sync(0xffffffffu, p, o);
    if (l == 0) {
        float x = g_as[s] + g_ad[d];
        float wf = x >= 0.f ? x : 0.01f * x;      // leaky_relu(slope 0.01)
        int pos = atomicAdd(&g_pos[d], 1);
        g_ef[pos] = wf;
        g_et[pos] = p;
        g_src2[pos] = s;
    }
}

// ---------------------------------------------------------------------------
// K5: per-dst segment: softmax (no atomics) + z accumulation in registers
__global__ void k_seg(const float* __restrict__ h, int n) {
    int gt = blockIdx.x * blockDim.x + threadIdx.x;
    int w = gt >> 5, lane = gt & 31;
    if (w >= n) return;
    int r0 = g_off[w], r1 = g_pos[w];     // pos cursor == segment end now
    float2 acc = make_float2(0.f, 0.f);
    if (r1 > r0) {
        // segment max
        float mf = -INFINITY, mt = -INFINITY;
        for (int j = r0 + lane; j < r1; j += 32) {
            mf = fmaxf(mf, g_ef[j]);
            mt = fmaxf(mt, g_et[j]);
        }
#pragma unroll
        for (int o = 16; o; o >>= 1) {
            mf = fmaxf(mf, __shfl_xor_sync(0xffffffffu, mf, o));
            mt = fmaxf(mt, __shfl_xor_sync(0xffffffffu, mt, o));
        }
        // exp + sums (write exps back; segment is contiguous & L1/L2 hot)
        float sf = 0.f, st = 0.f;
        for (int j = r0 + lane; j < r1; j += 32) {
            float a = __expf(g_ef[j] - mf);
            float b = __expf(g_et[j] - mt);
            sf += a; st += b;
            g_ef[j] = a; g_et[j] = b;
        }
#pragma unroll
        for (int o = 16; o; o >>= 1) {
            sf += __shfl_xor_sync(0xffffffffu, sf, o);
            st += __shfl_xor_sync(0xffffffffu, st, o);
        }
        float isf = 0.5f / sf, ist = 0.5f / st;
        // alpha into g_ef
        for (int j = r0 + lane; j < r1; j += 32)
            g_ef[j] = g_ef[j] * isf + g_et[j] * ist;
        __syncwarp();
        // accumulate z row: warp cooperates per edge, unrolled for MLP
        int j = r0;
#pragma unroll 1
        for (; j + 4 <= r1; j += 4) {
            float al0 = g_ef[j],     al1 = g_ef[j + 1];
            float al2 = g_ef[j + 2], al3 = g_ef[j + 3];
            int s0 = g_src2[j],     s1 = g_src2[j + 1];
            int s2 = g_src2[j + 2], s3 = g_src2[j + 3];
            float2 h0 = *reinterpret_cast<const float2*>(h + (size_t)s0 * DD + lane * 2);
            float2 h1 = *reinterpret_cast<const float2*>(h + (size_t)s1 * DD + lane * 2);
            float2 h2 = *reinterpret_cast<const float2*>(h + (size_t)s2 * DD + lane * 2);
            float2 h3 = *reinterpret_cast<const float2*>(h + (size_t)s3 * DD + lane * 2);
            acc.x += al0 * h0.x + al1 * h1.x + al2 * h2.x + al3 * h3.x;
            acc.y += al0 * h0.y + al1 * h1.y + al2 * h2.y + al3 * h3.y;
        }
        for (; j < r1; j++) {
            float al = g_ef[j];
            int s = g_src2[j];
            float2 hv = *reinterpret_cast<const float2*>(h + (size_t)s * DD + lane * 2);
            acc.x += al * hv.x;
            acc.y += al * hv.y;
        }
    }
    *reinterpret_cast<float2*>(g_z + (size_t)w * DD + lane * 2) = acc;
}

// ---------------------------------------------------------------------------
// K6: out = z @ W^T + b   (block = (64,4); W transposed in smem, conflict-free)
__global__ void k_out(const float* __restrict__ Ww, const float* __restrict__ Wb,
                      float* __restrict__ out, int n) {
    __shared__ float Ws[DD * DD];   // Ws[k*64 + c] = Ww[c*64 + k]
    __shared__ float bs[DD];
    int tid = threadIdx.y * 64 + threadIdx.x;
    for (int i = tid; i < DD * DD; i += 256) {
        int c = i >> 6, k = i & 63;
        Ws[k * DD + c] = Ww[i];
    }
    if (tid < DD) bs[tid] = Wb[tid];
    __syncthreads();
    int row = blockIdx.x * 4 + threadIdx.y;
    if (row >= n) return;
    int c = threadIdx.x;
    const float* zr = g_z + (size_t)row * DD;
    float acc = bs[c];
#pragma unroll
    for (int k = 0; k < DD; k += 4) {
        float4 zv = *reinterpret_cast<const float4*>(zr + k);
        acc += zv.x * Ws[(k + 0) * DD + c];
        acc += zv.y * Ws[(k + 1) * DD + c];
        acc += zv.z * Ws[(k + 2) * DD + c];
        acc += zv.w * Ws[(k + 3) * DD + c];
    }
    out[(size_t)row * DD + c] = acc;
}

// ---------------------------------------------------------------------------
extern "C" void kernel_launch(void* const* d_in, const int* in_sizes, int n_in,
                              void* d_out, int out_size) {
    const float* h   = (const float*)d_in[0];
    const float* tax = (const float*)d_in[1];
    const int*   src = (const int*)d_in[2];
    const int*   dst = (const int*)d_in[3];
    const float* wh  = (const float*)d_in[4];
    const float* Ww  = (const float*)d_in[5];
    const float* Wb  = (const float*)d_in[6];
    float* out = (float*)d_out;

    int n = in_sizes[0] / DD;
    int e = in_sizes[2];

    k_init<<<(n + 255) / 256, 256>>>(n);
    k_node<<<(int)(((long long)n * 32 + 255) / 256), 256>>>(h, wh, n);
    k_hist<<<(e + 255) / 256, 256>>>(dst, e);
    k_scan<<<1, 1024>>>(n);
    k_edge1<<<(int)(((long long)e * 8 + 255) / 256), 256>>>(tax, src, dst, e);
    k_seg<<<(int)(((long long)n * 32 + 255) / 256), 256>>>(h, n);
    k_out<<<(n + 3) / 4, dim3(64, 4)>>>(Ww, Wb, out, n);
}

// round 5
// speedup vs baseline: 1.3718x; 1.2489x over previous
#include <cuda_runtime.h>
#include <math.h>

static constexpr int NN = 100000;   // nodes (capacity)
static constexpr int EE = 1600000;  // edges (capacity)
static constexpr int DD = 64;
static constexpr int SCAN_B = 1024;                 // elements per scan block
static constexpr int NB_MAX = (NN + SCAN_B - 1) / SCAN_B;

// Scratch (static device globals; no allocation anywhere)
__device__ __align__(16) float g_z[(size_t)NN * DD];   // 25.6 MB z accumulator
__device__ float g_as[NN], g_ad[NN];                   // per-node logit halves
__device__ int   g_cnt[NN];                            // in-degree histogram
__device__ int   g_off[NN];                            // CSR row start
__device__ int   g_pos[NN];                            // scatter cursor -> row end
__device__ float g_ef[EE], g_et[EE];                   // logits -> exps -> alpha
__device__ int   g_src2[EE];                           // src sorted by dst
__device__ int   g_bsum[NB_MAX];                       // per-block count sums -> prefixes

// ---------------------------------------------------------------------------
// K0: zero histogram
__global__ void k_init(int n) {
    int i = blockIdx.x * blockDim.x + threadIdx.x;
    if (i < n) g_cnt[i] = 0;
}

// ---------------------------------------------------------------------------
// K1: per-node a_s = h[n] . wh[0:64], a_d = h[n] . wh[64:128]  (warp/node)
__global__ void k_node(const float* __restrict__ h, const float* __restrict__ wh, int n) {
    int gt = blockIdx.x * blockDim.x + threadIdx.x;
    int w = gt >> 5, lane = gt & 31;
    if (w >= n) return;
    float2 hv = *reinterpret_cast<const float2*>(h + (size_t)w * DD + lane * 2);
    float2 wa = *reinterpret_cast<const float2*>(wh + lane * 2);
    float2 wb = *reinterpret_cast<const float2*>(wh + DD + lane * 2);
    float ps = hv.x * wa.x + hv.y * wa.y;
    float pd = hv.x * wb.x + hv.y * wb.y;
#pragma unroll
    for (int o = 16; o; o >>= 1) {
        ps += __shfl_xor_sync(0xffffffffu, ps, o);
        pd += __shfl_xor_sync(0xffffffffu, pd, o);
    }
    if (lane == 0) { g_as[w] = ps; g_ad[w] = pd; }
}

// ---------------------------------------------------------------------------
// K2: histogram of dst
__global__ void k_hist(const int* __restrict__ dst, int e) {
    int i = blockIdx.x * blockDim.x + threadIdx.x;
    if (i < e) atomicAdd(&g_cnt[dst[i]], 1);
}

// ---------------------------------------------------------------------------
// K3a: per-block sums of g_cnt (1024 counts per block, shared tree reduce)
__global__ void k_blocksum(int n) {
    __shared__ int sh[SCAN_B];
    int i = blockIdx.x * SCAN_B + threadIdx.x;
    sh[threadIdx.x] = (i < n) ? g_cnt[i] : 0;
    __syncthreads();
#pragma unroll
    for (int s = SCAN_B / 2; s > 0; s >>= 1) {
        if (threadIdx.x < s) sh[threadIdx.x] += sh[threadIdx.x + s];
        __syncthreads();
    }
    if (threadIdx.x == 0) g_bsum[blockIdx.x] = sh[0];
}

// K3b: exclusive scan of block sums (single tiny block; nb <= 128)
__global__ void k_scanb(int nb) {
    __shared__ int sh[128];
    int t = threadIdx.x;
    int v = (t < nb) ? g_bsum[t] : 0;
    sh[t] = v;
    __syncthreads();
#pragma unroll
    for (int d = 1; d < 128; d <<= 1) {
        int u = (t >= d) ? sh[t - d] : 0;
        __syncthreads();
        sh[t] += u;
        __syncthreads();
    }
    if (t < nb) g_bsum[t] = sh[t] - v;   // exclusive prefix
}

// K3c: in-block exclusive scan + block prefix -> g_off, g_pos
__global__ void k_apply(int n) {
    __shared__ int sh[SCAN_B];
    int i = blockIdx.x * SCAN_B + threadIdx.x;
    int v = (i < n) ? g_cnt[i] : 0;
    sh[threadIdx.x] = v;
    __syncthreads();
#pragma unroll
    for (int d = 1; d < SCAN_B; d <<= 1) {
        int u = (threadIdx.x >= d) ? sh[threadIdx.x - d] : 0;
        __syncthreads();
        sh[threadIdx.x] += u;
        __syncthreads();
    }
    if (i < n) {
        int off = g_bsum[blockIdx.x] + sh[threadIdx.x] - v;   // exclusive
        g_off[i] = off;
        g_pos[i] = off;
    }
}

// ---------------------------------------------------------------------------
// K4: per-edge logits, scattered into CSR order (8 lanes/edge, float4 loads)
__global__ void k_edge1(const float* __restrict__ tax, const int* __restrict__ src,
                        const int* __restrict__ dst, int e) {
    int gt = blockIdx.x * blockDim.x + threadIdx.x;
    int w = gt >> 3, l = gt & 7;
    if (w >= e) return;
    int s = src[w], d = dst[w];
    const float4* ts = reinterpret_cast<const float4*>(tax + (size_t)s * DD);
    const float4* td = reinterpret_cast<const float4*>(tax + (size_t)d * DD);
    float4 a0 = ts[l * 2],     b0 = td[l * 2];
    float4 a1 = ts[l * 2 + 1], b1 = td[l * 2 + 1];
    float p = a0.x * b0.x + a0.y * b0.y + a0.z * b0.z + a0.w * b0.w
            + a1.x * b1.x + a1.y * b1.y + a1.z * b1.z + a1.w * b1.w;
#pragma unroll
    for (int o = 4; o; o >>= 1) p += __shfl_xor_sync(0xffffffffu, p, o);
    if (l == 0) {
        float x = g_as[s] + g_ad[d];
        float wf = x >= 0.f ? x : 0.01f * x;      // leaky_relu(slope 0.01)
        int pos = atomicAdd(&g_pos[d], 1);
        g_ef[pos] = wf;
        g_et[pos] = p;
        g_src2[pos] = s;
    }
}

// ---------------------------------------------------------------------------
// K5: per-dst segment: softmax (no atomics) + z accumulation in registers
__global__ void k_seg(const float* __restrict__ h, int n) {
    int gt = blockIdx.x * blockDim.x + threadIdx.x;
    int w = gt >> 5, lane = gt & 31;
    if (w >= n) return;
    int r0 = g_off[w], r1 = g_pos[w];     // pos cursor == segment end now
    float2 acc = make_float2(0.f, 0.f);
    if (r1 > r0) {
        // segment max
        float mf = -INFINITY, mt = -INFINITY;
        for (int j = r0 + lane; j < r1; j += 32) {
            mf = fmaxf(mf, g_ef[j]);
            mt = fmaxf(mt, g_et[j]);
        }
#pragma unroll
        for (int o = 16; o; o >>= 1) {
            mf = fmaxf(mf, __shfl_xor_sync(0xffffffffu, mf, o));
            mt = fmaxf(mt, __shfl_xor_sync(0xffffffffu, mt, o));
        }
        // exp + sums (write exps back; segment is contiguous & L1/L2 hot)
        float sf = 0.f, st = 0.f;
        for (int j = r0 + lane; j < r1; j += 32) {
            float a = __expf(g_ef[j] - mf);
            float b = __expf(g_et[j] - mt);
            sf += a; st += b;
            g_ef[j] = a; g_et[j] = b;
        }
#pragma unroll
        for (int o = 16; o; o >>= 1) {
            sf += __shfl_xor_sync(0xffffffffu, sf, o);
            st += __shfl_xor_sync(0xffffffffu, st, o);
        }
        float isf = 0.5f / sf, ist = 0.5f / st;
        // alpha into g_ef
        for (int j = r0 + lane; j < r1; j += 32)
            g_ef[j] = g_ef[j] * isf + g_et[j] * ist;
        __syncwarp();
        // accumulate z row: warp cooperates per edge, unrolled for MLP
        int j = r0;
#pragma unroll 1
        for (; j + 4 <= r1; j += 4) {
            float al0 = g_ef[j],     al1 = g_ef[j + 1];
            float al2 = g_ef[j + 2], al3 = g_ef[j + 3];
            int s0 = g_src2[j],     s1 = g_src2[j + 1];
            int s2 = g_src2[j + 2], s3 = g_src2[j + 3];
            float2 h0 = *reinterpret_cast<const float2*>(h + (size_t)s0 * DD + lane * 2);
            float2 h1 = *reinterpret_cast<const float2*>(h + (size_t)s1 * DD + lane * 2);
            float2 h2 = *reinterpret_cast<const float2*>(h + (size_t)s2 * DD + lane * 2);
            float2 h3 = *reinterpret_cast<const float2*>(h + (size_t)s3 * DD + lane * 2);
            acc.x += al0 * h0.x + al1 * h1.x + al2 * h2.x + al3 * h3.x;
            acc.y += al0 * h0.y + al1 * h1.y + al2 * h2.y + al3 * h3.y;
        }
        for (; j < r1; j++) {
            float al = g_ef[j];
            int s = g_src2[j];
            float2 hv = *reinterpret_cast<const float2*>(h + (size_t)s * DD + lane * 2);
            acc.x += al * hv.x;
            acc.y += al * hv.y;
        }
    }
    *reinterpret_cast<float2*>(g_z + (size_t)w * DD + lane * 2) = acc;
}

// ---------------------------------------------------------------------------
// K6: out = z @ W^T + b   (block = (64,4); W transposed in smem, conflict-free)
__global__ void k_out(const float* __restrict__ Ww, const float* __restrict__ Wb,
                      float* __restrict__ out, int n) {
    __shared__ float Ws[DD * DD];   // Ws[k*64 + c] = Ww[c*64 + k]
    __shared__ float bs[DD];
    int tid = threadIdx.y * 64 + threadIdx.x;
    for (int i = tid; i < DD * DD; i += 256) {
        int c = i >> 6, k = i & 63;
        Ws[k * DD + c] = Ww[i];
    }
    if (tid < DD) bs[tid] = Wb[tid];
    __syncthreads();
    int row = blockIdx.x * 4 + threadIdx.y;
    if (row >= n) return;
    int c = threadIdx.x;
    const float* zr = g_z + (size_t)row * DD;
    float acc = bs[c];
#pragma unroll
    for (int k = 0; k < DD; k += 4) {
        float4 zv = *reinterpret_cast<const float4*>(zr + k);
        acc += zv.x * Ws[(k + 0) * DD + c];
        acc += zv.y * Ws[(k + 1) * DD + c];
        acc += zv.z * Ws[(k + 2) * DD + c];
        acc += zv.w * Ws[(k + 3) * DD + c];
    }
    out[(size_t)row * DD + c] = acc;
}

// ---------------------------------------------------------------------------
extern "C" void kernel_launch(void* const* d_in, const int* in_sizes, int n_in,
                              void* d_out, int out_size) {
    const float* h   = (const float*)d_in[0];
    const float* tax = (const float*)d_in[1];
    const int*   src = (const int*)d_in[2];
    const int*   dst = (const int*)d_in[3];
    const float* wh  = (const float*)d_in[4];
    const float* Ww  = (const float*)d_in[5];
    const float* Wb  = (const float*)d_in[6];
    float* out = (float*)d_out;

    int n = in_sizes[0] / DD;
    int e = in_sizes[2];
    int nb = (n + SCAN_B - 1) / SCAN_B;   // <= 128 for N=100K

    k_init<<<(n + 255) / 256, 256>>>(n);
    k_node<<<(int)(((long long)n * 32 + 255) / 256), 256>>>(h, wh, n);
    k_hist<<<(e + 255) / 256, 256>>>(dst, e);
    k_blocksum<<<nb, SCAN_B>>>(n);
    k_scanb<<<1, 128>>>(nb);
    k_apply<<<nb, SCAN_B>>>(n);
    k_edge1<<<(int)(((long long)e * 8 + 255) / 256), 256>>>(tax, src, dst, e);
    k_seg<<<(int)(((long long)n * 32 + 255) / 256), 256>>>(h, n);
    k_out<<<(n + 3) / 4, dim3(64, 4)>>>(Ww, Wb, out, n);
}